// round 3
// baseline (speedup 1.0000x reference)
#include <cuda_runtime.h>
#include <cuda_bf16.h>

#define DAMPING_PARAM 0.7f
#define N_NODES_MAX 100000

// Scratch accumulator: one float4 slot per node (xyz + pad), 16B aligned.
__device__ float4 g_accum[N_NODES_MAX];

__global__ void zero_scratch_kernel(int n_nodes) {
    int i = blockIdx.x * blockDim.x + threadIdx.x;
    if (i < n_nodes) g_accum[i] = make_float4(0.f, 0.f, 0.f, 0.f);
}

__global__ __launch_bounds__(256) void electric_field_kernel(
    const int* __restrict__ edge_src,
    const int* __restrict__ edge_dst,
    const float* __restrict__ distances,
    const float* __restrict__ vec,
    const float* __restrict__ charges,
    const float* __restrict__ polarisability,
    int n_edges)
{
    int e = blockIdx.x * blockDim.x + threadIdx.x;
    if (e >= n_edges) return;

    int src = edge_src[e];
    int dst = edge_dst[e];
    float r = distances[e];

    float q  = __ldg(&charges[dst]);
    float pa = __ldg(&polarisability[src]);
    float pb = __ldg(&polarisability[dst]);

    float alpha = pa * pb;
    // u = r * alpha^(-1/6)
    float u = r * __expf(-__logf(alpha) * (1.0f / 6.0f));
    // damping = 1 - exp(-0.7 * u^1.5)
    float u15 = u * __fsqrt_rn(u);
    float damping = 1.0f - __expf(-DAMPING_PARAM * u15);
    // coeff = -q * damping / r^3
    float inv_r = __fdividef(1.0f, r);
    float coeff = -q * damping * inv_r * inv_r * inv_r;

    float vx = vec[3 * e + 0];
    float vy = vec[3 * e + 1];
    float vz = vec[3 * e + 2];

    // Single 16B vector reduction instead of 3 scalar atomics.
    float4* slot = &g_accum[src];
    asm volatile(
        "red.global.add.v4.f32 [%0], {%1, %2, %3, %4};"
        :: "l"(slot), "f"(coeff * vx), "f"(coeff * vy), "f"(coeff * vz), "f"(0.0f)
        : "memory");
}

__global__ void compact_kernel(float* __restrict__ out, int n_nodes) {
    int i = blockIdx.x * blockDim.x + threadIdx.x;
    if (i < n_nodes) {
        float4 a = g_accum[i];
        out[3 * i + 0] = a.x;
        out[3 * i + 1] = a.y;
        out[3 * i + 2] = a.z;
    }
}

extern "C" void kernel_launch(void* const* d_in, const int* in_sizes, int n_in,
                              void* d_out, int out_size) {
    // inputs: species[N], edge_src[E], edge_dst[E], distances[E], vec[E*3],
    //         charges[N], polarisability[N]
    const int*   edge_src = (const int*)d_in[1];
    const int*   edge_dst = (const int*)d_in[2];
    const float* dist     = (const float*)d_in[3];
    const float* vec      = (const float*)d_in[4];
    const float* charges  = (const float*)d_in[5];
    const float* pol      = (const float*)d_in[6];
    float* out = (float*)d_out;

    int n_edges = in_sizes[1];
    int n_nodes = in_sizes[0];

    zero_scratch_kernel<<<(n_nodes + 255) / 256, 256>>>(n_nodes);

    electric_field_kernel<<<(n_edges + 255) / 256, 256>>>(
        edge_src, edge_dst, dist, vec, charges, pol, n_edges);

    compact_kernel<<<(n_nodes + 255) / 256, 256>>>(out, n_nodes);
}

// round 4
// speedup vs baseline: 1.3852x; 1.3852x over previous
#include <cuda_runtime.h>
#include <cuda_bf16.h>

#define DAMPING_PARAM 0.7f
#define N_NODES_MAX 100000

// Per-node accumulator: float4 slot (xyz + pad), 16B aligned.
__device__ float4 g_accum[N_NODES_MAX];
// Per-node precomputed data: {charge, pol^(-1/6)}
__device__ float2 g_node[N_NODES_MAX];

__global__ void prep_kernel(const float* __restrict__ charges,
                            const float* __restrict__ pol,
                            int n_nodes) {
    int i = blockIdx.x * blockDim.x + threadIdx.x;
    if (i < n_nodes) {
        g_accum[i] = make_float4(0.f, 0.f, 0.f, 0.f);
        float p = pol[i];
        float ipol = __expf(-__logf(p) * (1.0f / 6.0f));  // p^(-1/6)
        g_node[i] = make_float2(charges[i], ipol);
    }
}

__device__ __forceinline__ void edge_accum(int src, int dst, float r,
                                           float vx, float vy, float vz) {
    float2 nd = __ldg(&g_node[dst]);            // {q, ipol_dst} one 8B gather
    float ipol_s = __ldg(&g_node[src].y);       // 4B gather, same array

    float u = r * ipol_s * nd.y;                // r * (pa*pb)^(-1/6)
    float u15 = u * __fsqrt_rn(u);
    float damping = 1.0f - __expf(-DAMPING_PARAM * u15);
    float inv_r = __fdividef(1.0f, r);
    float coeff = -nd.x * damping * inv_r * inv_r * inv_r;

    float4* slot = &g_accum[src];
    asm volatile("red.global.add.v2.f32 [%0], {%1, %2};"
                 :: "l"(slot), "f"(coeff * vx), "f"(coeff * vy) : "memory");
    asm volatile("red.global.add.f32 [%0], %1;"
                 :: "l"(&slot->z), "f"(coeff * vz) : "memory");
}

__global__ __launch_bounds__(256) void electric_field_kernel(
    const int* __restrict__ edge_src,
    const int* __restrict__ edge_dst,
    const float* __restrict__ distances,
    const float* __restrict__ vec,
    int n_edges)
{
    int t = blockIdx.x * blockDim.x + threadIdx.x;
    int e0 = 2 * t;
    if (e0 + 1 < n_edges) {
        // Paired path: vectorized stream loads.
        int2   s2 = __ldg((const int2*)(edge_src) + t);
        int2   d2 = __ldg((const int2*)(edge_dst) + t);
        float2 r2 = __ldg((const float2*)(distances) + t);
        const float2* vf2 = (const float2*)vec + 3 * t;
        float2 v01 = __ldg(vf2 + 0);
        float2 v23 = __ldg(vf2 + 1);
        float2 v45 = __ldg(vf2 + 2);

        edge_accum(s2.x, d2.x, r2.x, v01.x, v01.y, v23.x);
        edge_accum(s2.y, d2.y, r2.y, v23.y, v45.x, v45.y);
    } else if (e0 < n_edges) {
        // Scalar tail.
        int src = edge_src[e0];
        int dst = edge_dst[e0];
        float r = distances[e0];
        edge_accum(src, dst, r, vec[3 * e0], vec[3 * e0 + 1], vec[3 * e0 + 2]);
    }
}

__global__ void compact_kernel(float* __restrict__ out, int n_nodes) {
    int i = blockIdx.x * blockDim.x + threadIdx.x;
    if (i < n_nodes) {
        float4 a = g_accum[i];
        out[3 * i + 0] = a.x;
        out[3 * i + 1] = a.y;
        out[3 * i + 2] = a.z;
    }
}

extern "C" void kernel_launch(void* const* d_in, const int* in_sizes, int n_in,
                              void* d_out, int out_size) {
    // inputs: species[N], edge_src[E], edge_dst[E], distances[E], vec[E*3],
    //         charges[N], polarisability[N]
    const int*   edge_src = (const int*)d_in[1];
    const int*   edge_dst = (const int*)d_in[2];
    const float* dist     = (const float*)d_in[3];
    const float* vec      = (const float*)d_in[4];
    const float* charges  = (const float*)d_in[5];
    const float* pol      = (const float*)d_in[6];
    float* out = (float*)d_out;

    int n_edges = in_sizes[1];
    int n_nodes = in_sizes[0];

    prep_kernel<<<(n_nodes + 255) / 256, 256>>>(charges, pol, n_nodes);

    int n_threads = (n_edges + 1) / 2;
    electric_field_kernel<<<(n_threads + 255) / 256, 256>>>(
        edge_src, edge_dst, dist, vec, n_edges);

    compact_kernel<<<(n_nodes + 255) / 256, 256>>>(out, n_nodes);
}

// round 6
// speedup vs baseline: 1.7815x; 1.2862x over previous
#include <cuda_runtime.h>
#include <cuda_bf16.h>

#define DAMPING_PARAM 0.7f
#define N_NODES_MAX 100000

// Per-node accumulator: float4 slot (xyz + pad), 16B aligned.
__device__ float4 g_accum[N_NODES_MAX];
// Per-node precomputed data: {charge, pol^(-1/6)}
__device__ float2 g_node[N_NODES_MAX];

__global__ void prep_kernel(const float* __restrict__ charges,
                            const float* __restrict__ pol,
                            int n_nodes) {
    int i = blockIdx.x * blockDim.x + threadIdx.x;
    if (i < n_nodes) {
        g_accum[i] = make_float4(0.f, 0.f, 0.f, 0.f);
        float p = pol[i];
        float ipol = __expf(-__logf(p) * (1.0f / 6.0f));  // p^(-1/6)
        g_node[i] = make_float2(charges[i], ipol);
    }
}

__device__ __forceinline__ void edge_accum(int src, int dst, float r,
                                           float vx, float vy, float vz) {
    float2 nd = __ldg(&g_node[dst]);            // {q, ipol_dst} one 8B gather
    float ipol_s = __ldg(&g_node[src].y);       // 4B gather, same array

    float u = r * ipol_s * nd.y;                // r * (pa*pb)^(-1/6)
    float u15 = u * __fsqrt_rn(u);
    float damping = 1.0f - __expf(-DAMPING_PARAM * u15);
    float inv_r = __fdividef(1.0f, r);
    float coeff = -nd.x * damping * inv_r * inv_r * inv_r;

    // One 16B atomic wavefront per edge.
    float4* slot = &g_accum[src];
    asm volatile("red.global.add.v4.f32 [%0], {%1, %2, %3, %4};"
                 :: "l"(slot), "f"(coeff * vx), "f"(coeff * vy),
                    "f"(coeff * vz), "f"(0.0f)
                 : "memory");
}

__global__ __launch_bounds__(256) void electric_field_kernel(
    const int* __restrict__ edge_src,
    const int* __restrict__ edge_dst,
    const float* __restrict__ distances,
    const float* __restrict__ vec,
    int n_edges)
{
    int t = blockIdx.x * blockDim.x + threadIdx.x;
    int e0 = 4 * t;
    if (e0 + 3 < n_edges) {
        // Streaming loads (evict-first) so the gather table stays in L1.
        int4   s4 = __ldcs((const int4*)(edge_src) + t);
        int4   d4 = __ldcs((const int4*)(edge_dst) + t);
        float4 r4 = __ldcs((const float4*)(distances) + t);
        const float4* vf4 = (const float4*)vec + 3 * t;
        float4 va = __ldcs(vf4 + 0);  // v0x v0y v0z v1x
        float4 vb = __ldcs(vf4 + 1);  // v1y v1z v2x v2y
        float4 vc = __ldcs(vf4 + 2);  // v2z v3x v3y v3z

        edge_accum(s4.x, d4.x, r4.x, va.x, va.y, va.z);
        edge_accum(s4.y, d4.y, r4.y, va.w, vb.x, vb.y);
        edge_accum(s4.z, d4.z, r4.z, vb.z, vb.w, vc.x);
        edge_accum(s4.w, d4.w, r4.w, vc.y, vc.z, vc.w);
    } else {
        for (int e = e0; e < n_edges; e++) {
            int src = edge_src[e];
            int dst = edge_dst[e];
            float r = distances[e];
            edge_accum(src, dst, r, vec[3 * e], vec[3 * e + 1], vec[3 * e + 2]);
        }
    }
}

__global__ void compact_kernel(float* __restrict__ out, int n_nodes) {
    int i = blockIdx.x * blockDim.x + threadIdx.x;
    if (i < n_nodes) {
        float4 a = g_accum[i];
        out[3 * i + 0] = a.x;
        out[3 * i + 1] = a.y;
        out[3 * i + 2] = a.z;
    }
}

extern "C" void kernel_launch(void* const* d_in, const int* in_sizes, int n_in,
                              void* d_out, int out_size) {
    // inputs: species[N], edge_src[E], edge_dst[E], distances[E], vec[E*3],
    //         charges[N], polarisability[N]
    const int*   edge_src = (const int*)d_in[1];
    const int*   edge_dst = (const int*)d_in[2];
    const float* dist     = (const float*)d_in[3];
    const float* vec      = (const float*)d_in[4];
    const float* charges  = (const float*)d_in[5];
    const float* pol      = (const float*)d_in[6];
    float* out = (float*)d_out;

    int n_edges = in_sizes[1];
    int n_nodes = in_sizes[0];

    prep_kernel<<<(n_nodes + 255) / 256, 256>>>(charges, pol, n_nodes);

    int n_threads = (n_edges + 3) / 4;
    electric_field_kernel<<<(n_threads + 255) / 256, 256>>>(
        edge_src, edge_dst, dist, vec, n_edges);

    compact_kernel<<<(n_nodes + 255) / 256, 256>>>(out, n_nodes);
}

// round 7
// speedup vs baseline: 1.9212x; 1.0784x over previous
#include <cuda_runtime.h>
#include <cuda_fp16.h>
#include <cuda_bf16.h>

#define DAMPING_PARAM 0.7f
#define N_NODES_MAX 100000

// Per-node accumulator: float4 slot (xyz + pad), 16B aligned.
__device__ float4 g_accum[N_NODES_MAX];
// Per-node packed table: {q (fp16), pol^(-1/6) (fp16)} -> 4B/node, 400KB total.
__device__ __half2 g_node[N_NODES_MAX];

__global__ void prep_kernel(const float* __restrict__ charges,
                            const float* __restrict__ pol,
                            int n_nodes) {
    int i = blockIdx.x * blockDim.x + threadIdx.x;
    if (i < n_nodes) {
        g_accum[i] = make_float4(0.f, 0.f, 0.f, 0.f);
        float p = pol[i];
        float ipol = __expf(-__logf(p) * (1.0f / 6.0f));  // p^(-1/6)
        g_node[i] = __floats2half2_rn(charges[i], ipol);
    }
}

__device__ __forceinline__ void edge_accum(int src, int dst, float r,
                                           float vx, float vy, float vz) {
    __half2 nd_h = __ldg(&g_node[dst]);             // {q, ipol_dst}, 4B gather
    float2 nd = __half22float2(nd_h);               // .x = q, .y = ipol_dst
    float ipol_s = __half2float(__ldg((const __half*)&g_node[src] + 1));

    float u = r * ipol_s * nd.y;                    // r * (pa*pb)^(-1/6)
    float u15 = u * __fsqrt_rn(u);
    float damping = 1.0f - __expf(-DAMPING_PARAM * u15);
    float inv_r = __fdividef(1.0f, r);
    float coeff = -nd.x * damping * inv_r * inv_r * inv_r;

    // One 16B atomic wavefront per edge.
    float4* slot = &g_accum[src];
    asm volatile("red.global.add.v4.f32 [%0], {%1, %2, %3, %4};"
                 :: "l"(slot), "f"(coeff * vx), "f"(coeff * vy),
                    "f"(coeff * vz), "f"(0.0f)
                 : "memory");
}

__global__ __launch_bounds__(256) void electric_field_kernel(
    const int* __restrict__ edge_src,
    const int* __restrict__ edge_dst,
    const float* __restrict__ distances,
    const float* __restrict__ vec,
    int n_edges)
{
    int t = blockIdx.x * blockDim.x + threadIdx.x;
    int e0 = 4 * t;
    if (e0 + 3 < n_edges) {
        // Streaming loads (evict-first) so the gather table stays in L1.
        int4   s4 = __ldcs((const int4*)(edge_src) + t);
        int4   d4 = __ldcs((const int4*)(edge_dst) + t);
        float4 r4 = __ldcs((const float4*)(distances) + t);
        const float4* vf4 = (const float4*)vec + 3 * t;
        float4 va = __ldcs(vf4 + 0);  // v0x v0y v0z v1x
        float4 vb = __ldcs(vf4 + 1);  // v1y v1z v2x v2y
        float4 vc = __ldcs(vf4 + 2);  // v2z v3x v3y v3z

        edge_accum(s4.x, d4.x, r4.x, va.x, va.y, va.z);
        edge_accum(s4.y, d4.y, r4.y, va.w, vb.x, vb.y);
        edge_accum(s4.z, d4.z, r4.z, vb.z, vb.w, vc.x);
        edge_accum(s4.w, d4.w, r4.w, vc.y, vc.z, vc.w);
    } else {
        for (int e = e0; e < n_edges; e++) {
            int src = edge_src[e];
            int dst = edge_dst[e];
            float r = distances[e];
            edge_accum(src, dst, r, vec[3 * e], vec[3 * e + 1], vec[3 * e + 2]);
        }
    }
}

__global__ void compact_kernel(float* __restrict__ out, int n_nodes) {
    int i = blockIdx.x * blockDim.x + threadIdx.x;
    if (i < n_nodes) {
        float4 a = g_accum[i];
        out[3 * i + 0] = a.x;
        out[3 * i + 1] = a.y;
        out[3 * i + 2] = a.z;
    }
}

extern "C" void kernel_launch(void* const* d_in, const int* in_sizes, int n_in,
                              void* d_out, int out_size) {
    // inputs: species[N], edge_src[E], edge_dst[E], distances[E], vec[E*3],
    //         charges[N], polarisability[N]
    const int*   edge_src = (const int*)d_in[1];
    const int*   edge_dst = (const int*)d_in[2];
    const float* dist     = (const float*)d_in[3];
    const float* vec      = (const float*)d_in[4];
    const float* charges  = (const float*)d_in[5];
    const float* pol      = (const float*)d_in[6];
    float* out = (float*)d_out;

    int n_edges = in_sizes[1];
    int n_nodes = in_sizes[0];

    prep_kernel<<<(n_nodes + 255) / 256, 256>>>(charges, pol, n_nodes);

    int n_threads = (n_edges + 3) / 4;
    electric_field_kernel<<<(n_threads + 255) / 256, 256>>>(
        edge_src, edge_dst, dist, vec, n_edges);

    compact_kernel<<<(n_nodes + 255) / 256, 256>>>(out, n_nodes);
}